// round 8
// baseline (speedup 1.0000x reference)
#include <cuda_runtime.h>
#include <cuda_fp16.h>
#include <cstdint>

// Problem constants
#define HW   4096
#define CCH  64
#define CQD  8
#define NBAT 4
#define NSPL 4          // denom j-split
#define NS   4          // attn key-split
#define NC   (HW / (NS * 128))   // chunks per attn block = 8
#define PSZ  (NBAT * CCH * HW)
#define L2E  1.4426950408889634f

// Scratch (device globals — no allocation allowed)
__device__ __half g_Qh[NBAT * HW * CQD];      // [b][m][8] fp16, pre-scaled by log2(e)
__device__ __half g_Kh[NBAT * HW * CQD];      // [b][n][8] fp16
__device__ __half g_Vh[NBAT * CCH * HW];      // [b][c][m] fp16 (vscale: *= 4096/denom[m])
__device__ float  g_dpart[NSPL * NBAT * HW];  // per-split softmax denominators
__device__ float  g_Dp[NS * PSZ];             // attn split partials [s][b][c][n]

// ---------------------------------------------------------------------------
// helpers
// ---------------------------------------------------------------------------
__device__ __forceinline__ unsigned long long pack2(float lo, float hi) {
    unsigned long long r;
    asm("mov.b64 %0, {%1, %2};" : "=l"(r) : "f"(lo), "f"(hi));
    return r;
}
__device__ __forceinline__ void unpack2(unsigned long long v, float& lo, float& hi) {
    asm("mov.b64 {%0, %1}, %2;" : "=f"(lo), "=f"(hi) : "l"(v));
}
__device__ __forceinline__ unsigned long long fma2(unsigned long long a,
                                                   unsigned long long b,
                                                   unsigned long long c) {
    unsigned long long d;
    asm("fma.rn.f32x2 %0, %1, %2, %3;" : "=l"(d) : "l"(a), "l"(b), "l"(c));
    return d;
}
__device__ __forceinline__ uint32_t smem_u32(const void* p) {
    uint32_t a;
    asm("{ .reg .u64 t; cvta.to.shared.u64 t, %1; cvt.u32.u64 %0, t; }" : "=r"(a) : "l"(p));
    return a;
}
__device__ __forceinline__ void ldsm2(uint32_t* r, uint32_t addr) {
    asm volatile("ldmatrix.sync.aligned.m8n8.x2.shared.b16 {%0,%1}, [%2];"
                 : "=r"(r[0]), "=r"(r[1]) : "r"(addr));
}
__device__ __forceinline__ void ldsm4(uint32_t* r, uint32_t addr) {
    asm volatile("ldmatrix.sync.aligned.m8n8.x4.shared.b16 {%0,%1,%2,%3}, [%4];"
                 : "=r"(r[0]), "=r"(r[1]), "=r"(r[2]), "=r"(r[3]) : "r"(addr));
}
__device__ __forceinline__ void mma8(float& d0, float& d1, float& d2, float& d3,
                                     const uint32_t* a, uint32_t b) {
    asm volatile("mma.sync.aligned.m16n8k8.row.col.f32.f16.f16.f32 "
                 "{%0,%1,%2,%3}, {%4,%5}, {%6}, {%0,%1,%2,%3};"
                 : "+f"(d0), "+f"(d1), "+f"(d2), "+f"(d3)
                 : "r"(a[0]), "r"(a[1]), "r"(b));
}
__device__ __forceinline__ void mma16(float* d, const uint32_t* a,
                                      uint32_t b0, uint32_t b1) {
    asm volatile("mma.sync.aligned.m16n8k16.row.col.f32.f16.f16.f32 "
                 "{%0,%1,%2,%3}, {%4,%5,%6,%7}, {%8,%9}, {%0,%1,%2,%3};"
                 : "+f"(d[0]), "+f"(d[1]), "+f"(d[2]), "+f"(d[3])
                 : "r"(a[0]), "r"(a[1]), "r"(a[2]), "r"(a[3]), "r"(b0), "r"(b1));
}
__device__ __forceinline__ uint32_t cvt_h2(float lo, float hi) {
    uint32_t r;
    asm("cvt.rn.f16x2.f32 %0, %1, %2;" : "=r"(r) : "f"(hi), "f"(lo));
    return r;
}
__device__ __forceinline__ uint32_t h2ex2(uint32_t a) {
    uint32_t r;
    asm("ex2.approx.f16x2 %0, %1;" : "=r"(r) : "r"(a));
    return r;
}
__device__ __forceinline__ uint32_t hadd2_(uint32_t a, uint32_t b) {
    uint32_t r;
    asm("add.f16x2 %0, %1, %2;" : "=r"(r) : "r"(a), "r"(b));
    return r;
}
__device__ __forceinline__ void cp16(uint32_t smem, const void* g) {
    asm volatile("cp.async.cg.shared.global [%0], [%1], 16;" :: "r"(smem), "l"(g));
}
#define CP_COMMIT() asm volatile("cp.async.commit_group;" ::: "memory")
#define CP_WAIT(n)  asm volatile("cp.async.wait_group %0;" :: "n"(n) : "memory")

// ---------------------------------------------------------------------------
// Kernel 1: QKV projections.  4 threads per pixel (h = channel group).
// ---------------------------------------------------------------------------
__global__ __launch_bounds__(512) void qkv_kernel(
    const float* __restrict__ x,
    const float* __restrict__ Wq, const float* __restrict__ bq,
    const float* __restrict__ Wk, const float* __restrict__ bk,
    const float* __restrict__ Wv, const float* __restrict__ bv)
{
    __shared__ float WqT[CCH][CQD];
    __shared__ float WkT[CCH][CQD];
    __shared__ float WvT[CCH][CCH];

    const int t = threadIdx.x;
    for (int i = t; i < CCH * CQD; i += 512) {
        int o = i / CCH, c = i % CCH;
        WqT[c][o] = Wq[i] * L2E;
        WkT[c][o] = Wk[i];
    }
    for (int i = t; i < CCH * CCH; i += 512) {
        int o = i / CCH, c = i % CCH;
        WvT[c][o] = Wv[i];
    }
    __syncthreads();

    const int b  = blockIdx.y;
    const int px = t & 127;
    const int h  = t >> 7;
    const int n  = blockIdx.x * 128 + px;
    const float* xp = x + (size_t)b * CCH * HW + n;

    unsigned long long va[8], qa[4], ka[4];
#pragma unroll
    for (int i = 0; i < 8; i++) va[i] = pack2(bv[16 * h + 2 * i], bv[16 * h + 2 * i + 1]);
    if (h == 0) {
#pragma unroll
        for (int i = 0; i < 4; i++) qa[i] = pack2(bq[2 * i] * L2E, bq[2 * i + 1] * L2E);
    }
    if (h == 1) {
#pragma unroll
        for (int i = 0; i < 4; i++) ka[i] = pack2(bk[2 * i], bk[2 * i + 1]);
    }

#pragma unroll 4
    for (int c = 0; c < CCH; c++) {
        float xv = xp[(size_t)c * HW];
        unsigned long long xx = pack2(xv, xv);
        const unsigned long long* wv2 = (const unsigned long long*)&WvT[c][16 * h];
#pragma unroll
        for (int i = 0; i < 8; i++) va[i] = fma2(xx, wv2[i], va[i]);
        if (h == 0) {
            const unsigned long long* wq2 = (const unsigned long long*)WqT[c];
#pragma unroll
            for (int i = 0; i < 4; i++) qa[i] = fma2(xx, wq2[i], qa[i]);
        }
        if (h == 1) {
            const unsigned long long* wk2 = (const unsigned long long*)WkT[c];
#pragma unroll
            for (int i = 0; i < 4; i++) ka[i] = fma2(xx, wk2[i], ka[i]);
        }
    }

    __half* Vp = g_Vh + ((size_t)b * CCH + 16 * h) * HW + n;
#pragma unroll
    for (int i = 0; i < 8; i++) {
        float lo, hi;
        unpack2(va[i], lo, hi);
        Vp[(size_t)(2 * i) * HW]     = __float2half(lo);
        Vp[(size_t)(2 * i + 1) * HW] = __float2half(hi);
    }
    if (h == 0) {
        uint32_t u[4];
#pragma unroll
        for (int i = 0; i < 4; i++) {
            float lo, hi;
            unpack2(qa[i], lo, hi);
            u[i] = cvt_h2(lo, hi);
        }
        *(uint4*)(g_Qh + ((size_t)b * HW + n) * CQD) = make_uint4(u[0], u[1], u[2], u[3]);
    }
    if (h == 1) {
        uint32_t u[4];
#pragma unroll
        for (int i = 0; i < 4; i++) {
            float lo, hi;
            unpack2(ka[i], lo, hi);
            u[i] = cvt_h2(lo, hi);
        }
        *(uint4*)(g_Kh + ((size_t)b * HW + n) * CQD) = make_uint4(u[0], u[1], u[2], u[3]);
    }
}

// ---------------------------------------------------------------------------
// Kernel 2: softmax denominators via MMA scores + f16x2 ex2.
// ---------------------------------------------------------------------------
__global__ __launch_bounds__(256) void denom_kernel()
{
    __shared__ __align__(16) uint8_t sm[4096];
    const uint32_t smb = smem_u32(sm);

    const int t = threadIdx.x, w = t >> 5, l = t & 31;
    const int b = blockIdx.z, s = blockIdx.y;
    const int mbase = blockIdx.x * 128;

    const uint4* Qg = (const uint4*)(g_Qh + (size_t)b * HW * CQD);
    const uint4* Kg = (const uint4*)(g_Kh + (size_t)b * HW * CQD);

    if (t < 128) *(uint4*)(sm + t * 16) = Qg[mbase + t];
    __syncthreads();
    uint32_t qa[2];
    ldsm2(qa, smb + (16 * w + (l & 15)) * 16);

    float rs0 = 0.0f, rs1 = 0.0f;
    for (int ch = 0; ch < (HW / NSPL) / 128; ch++) {
        const int nn0 = s * (HW / NSPL) + ch * 128;
        __syncthreads();
        if (t < 128) *(uint4*)(sm + 2048 + t * 16) = Kg[nn0 + t];
        __syncthreads();
        uint32_t kb[16];
        ldsm4(kb + 0,  smb + 2048 + l * 16);
        ldsm4(kb + 4,  smb + 2048 + (32 + l) * 16);
        ldsm4(kb + 8,  smb + 2048 + (64 + l) * 16);
        ldsm4(kb + 12, smb + 2048 + (96 + l) * 16);
        uint32_t a0 = 0u, a1 = 0u;
#pragma unroll
        for (int j = 0; j < 16; j++) {
            float d0 = 0, d1 = 0, d2 = 0, d3 = 0;
            mma8(d0, d1, d2, d3, qa, kb[j]);
            a0 = hadd2_(a0, h2ex2(cvt_h2(d0, d1)));
            a1 = hadd2_(a1, h2ex2(cvt_h2(d2, d3)));
        }
        float2 f0 = __half22float2(*reinterpret_cast<__half2*>(&a0));
        float2 f1 = __half22float2(*reinterpret_cast<__half2*>(&a1));
        rs0 += f0.x + f0.y;
        rs1 += f1.x + f1.y;
    }
    rs0 += __shfl_xor_sync(0xFFFFFFFFu, rs0, 1);
    rs0 += __shfl_xor_sync(0xFFFFFFFFu, rs0, 2);
    rs1 += __shfl_xor_sync(0xFFFFFFFFu, rs1, 1);
    rs1 += __shfl_xor_sync(0xFFFFFFFFu, rs1, 2);
    if ((l & 3) == 0) {
        const int r = 16 * w + (l >> 2);
        float* dst = g_dpart + ((size_t)s * NBAT + b) * HW + mbase;
        dst[r]     = rs0;
        dst[r + 8] = rs1;
    }
}

// ---------------------------------------------------------------------------
// Kernel 3: prescale V in place (half2): V[c][m] *= 4096/denom[m]
// ---------------------------------------------------------------------------
__global__ __launch_bounds__(256) void vscale_kernel()
{
    const int t = threadIdx.x;
    const int b = blockIdx.y;
    const int m2 = blockIdx.x * 256 + t;         // half2 index
    const int m = 2 * m2;
    float da = g_dpart[(size_t)b * HW + m]
             + g_dpart[((size_t)NBAT + b) * HW + m]
             + g_dpart[((size_t)2 * NBAT + b) * HW + m]
             + g_dpart[((size_t)3 * NBAT + b) * HW + m];
    float db = g_dpart[(size_t)b * HW + m + 1]
             + g_dpart[((size_t)NBAT + b) * HW + m + 1]
             + g_dpart[((size_t)2 * NBAT + b) * HW + m + 1]
             + g_dpart[((size_t)3 * NBAT + b) * HW + m + 1];
    const __half2 inv = __floats2half2_rn(__fdividef(4096.0f, da),
                                          __fdividef(4096.0f, db));
    __half2* Vp = (__half2*)(g_Vh + (size_t)b * CCH * HW) + m2;
#pragma unroll
    for (int c = 0; c < CCH; c++)
        Vp[(size_t)c * (HW / 2)] = __hmul2(Vp[(size_t)c * (HW / 2)], inv);
}

// ---------------------------------------------------------------------------
// Kernel 4: attention aggregation — fused score/MMA pipeline.
//   Q slab (all 8 chunks) staged once; V double-buffered (swizzled, no pad).
//   Inside the 8-step P@V loop, pa[kk] for the NEXT chunk is regenerated
//   right after being consumed, keeping the tensor pipe fed.
// SMEM (static 48KB): V0 @0 (16K) | V1 @16K | Qslab @32K (16K)
//   K bootstrapped through V0; epilogue f32 staging overlays base.
// ---------------------------------------------------------------------------
#define SM_V0 0
#define SM_V1 16384
#define SM_QS 32768
#define OSTR  65

__global__ __launch_bounds__(256, 3) void attn_kernel()
{
    __shared__ __align__(16) uint8_t sm[49152];
    const uint32_t smb = smem_u32(sm);

    const int t = threadIdx.x, w = t >> 5, l = t & 31;
    const int s = blockIdx.y;
    const int b = blockIdx.z;
    const int n0 = blockIdx.x * 128;

    const uint4* Kg = (const uint4*)(g_Kh + (size_t)b * HW * CQD);
    const uint4* Qg = (const uint4*)(g_Qh + (size_t)b * HW * CQD);
    const uint4* Vg = (const uint4*)(g_Vh + (size_t)b * CCH * HW);

    // bootstrap K tile through V0, stage Q slab async
    if (t < 128) *(uint4*)(sm + SM_V0 + t * 16) = Kg[n0 + t];
#pragma unroll
    for (int jj = 0; jj < 4; jj++) {
        int i = t + jj * 256;                         // 0..1023
        cp16(smb + SM_QS + i * 16, Qg + s * (NC * 128) + i);
    }
    CP_COMMIT();
    __syncthreads();
    uint32_t ka[2];
    ldsm2(ka, smb + SM_V0 + (16 * w + (l & 15)) * 16);
    CP_WAIT(0);
    __syncthreads();                                  // K consumed, Q slab visible

    // stage V chunk m0 into buffer (swizzled: chunk16 ^= row&7)
    auto stageV = [&](int buf, int m0) {
        const uint32_t vb = smb + (buf ? SM_V1 : SM_V0);
#pragma unroll
        for (int jj = 0; jj < 4; jj++) {
            int i = t + jj * 256;
            int row = i >> 4, c16 = i & 15;
            cp16(vb + row * 256 + ((c16 ^ (row & 7)) << 4),
                 Vg + (size_t)row * (HW / 8) + (m0 >> 3) + c16);
        }
    };
    stageV(0, s * NC * 128);
    CP_COMMIT();

    float dacc[8][4];
#pragma unroll
    for (int ct = 0; ct < 8; ct++)
#pragma unroll
        for (int i = 0; i < 4; i++) dacc[ct][i] = 0.0f;

    // prologue: pa for chunk 0 (from Q slab; overlaps V(0) load)
    uint32_t pa[8][4];
#pragma unroll
    for (int half = 0; half < 2; half++) {
        uint32_t qb[8];
        ldsm4(qb + 0, smb + SM_QS + (64 * half + l) * 16);
        ldsm4(qb + 4, smb + SM_QS + (64 * half + 32 + l) * 16);
#pragma unroll
        for (int j = 0; j < 8; j++) {
            float d0 = 0, d1 = 0, d2 = 0, d3 = 0;
            mma8(d0, d1, d2, d3, ka, qb[j]);
            const int jt = 8 * half + j;
            pa[jt >> 1][(jt & 1) * 2]     = h2ex2(cvt_h2(d0, d1));
            pa[jt >> 1][(jt & 1) * 2 + 1] = h2ex2(cvt_h2(d2, d3));
        }
    }

    for (int chunk = 0; chunk < NC; chunk++) {
        const int buf = chunk & 1;
        CP_WAIT(0);                 // V(chunk) arrived
        __syncthreads();            // ...visible to all; prev buffer free
        if (chunk + 1 < NC) {
            stageV(buf ^ 1, (s * NC + chunk + 1) * 128);
            CP_COMMIT();
        }

        const uint32_t vbase = smb + (buf ? SM_V1 : SM_V0);
        const uint32_t qsnxt = smb + SM_QS + (((chunk + 1) & (NC - 1)) << 11);

        uint32_t qb[4];
#pragma unroll
        for (int kk = 0; kk < 8; kk++) {
            // P@V for current chunk, k-step kk (consumes pa[kk])
#pragma unroll
            for (int cp = 0; cp < 4; cp++) {
                const int row = cp * 16 + ((l >> 4) << 3) + (l & 7);
                const int ch16 = kk * 2 + ((l >> 3) & 1);
                uint32_t bb[4];
                ldsm4(bb, vbase + row * 256 + ((ch16 ^ (row & 7)) << 4));
                mma16(dacc[2 * cp],     pa[kk], bb[0], bb[1]);
                mma16(dacc[2 * cp + 1], pa[kk], bb[2], bb[3]);
            }
            // regenerate pa[kk] for the NEXT chunk (WAR on same registers)
            if ((kk & 1) == 0)
                ldsm4(qb, qsnxt + (((kk >> 1) * 32) + l) * 16);
            {
                float d0 = 0, d1 = 0, d2 = 0, d3 = 0;
                mma8(d0, d1, d2, d3, ka, qb[(kk & 1) * 2]);
                pa[kk][0] = h2ex2(cvt_h2(d0, d1));
                pa[kk][1] = h2ex2(cvt_h2(d2, d3));
            }
            {
                float d0 = 0, d1 = 0, d2 = 0, d3 = 0;
                mma8(d0, d1, d2, d3, ka, qb[(kk & 1) * 2 + 1]);
                pa[kk][2] = h2ex2(cvt_h2(d0, d1));
                pa[kk][3] = h2ex2(cvt_h2(d2, d3));
            }
        }
    }

    // ---- stage partial D through smem, write [s][b][c][n] coalesced ----
    __syncthreads();
    float* sD = (float*)sm;
    const int r = l >> 2, q = l & 3;
#pragma unroll
    for (int ct = 0; ct < 8; ct++) {
        const int c = ct * 8 + 2 * q;
        sD[(16 * w + r) * OSTR + c]         = dacc[ct][0];
        sD[(16 * w + r) * OSTR + c + 1]     = dacc[ct][1];
        sD[(16 * w + r + 8) * OSTR + c]     = dacc[ct][2];
        sD[(16 * w + r + 8) * OSTR + c + 1] = dacc[ct][3];
    }
    __syncthreads();

    float* dst = g_Dp + (size_t)s * PSZ + (size_t)b * CCH * HW;
#pragma unroll
    for (int i = t; i < 128 * CCH; i += 256) {
        const int c = i >> 7, n = i & 127;
        dst[(size_t)c * HW + n0 + n] = sD[n * OSTR + c];
    }
}

// ---------------------------------------------------------------------------
// Kernel 5: combine split partials + gamma + residual (vectorized)
// ---------------------------------------------------------------------------
__global__ __launch_bounds__(256) void combine_kernel(
    const float* __restrict__ x,
    const float* __restrict__ gamma,
    float* __restrict__ out)
{
    const size_t i = ((size_t)blockIdx.x * 256 + threadIdx.x) * 4;
    const float gm = gamma[0] * (1.0f / 4096.0f);
    float4 a = *(const float4*)(g_Dp + i);
    float4 c = *(const float4*)(g_Dp + PSZ + i);
    float4 d = *(const float4*)(g_Dp + 2 * (size_t)PSZ + i);
    float4 e = *(const float4*)(g_Dp + 3 * (size_t)PSZ + i);
    float4 xv = *(const float4*)(x + i);
    float4 o;
    o.x = gm * ((a.x + c.x) + (d.x + e.x)) + xv.x;
    o.y = gm * ((a.y + c.y) + (d.y + e.y)) + xv.y;
    o.z = gm * ((a.z + c.z) + (d.z + e.z)) + xv.z;
    o.w = gm * ((a.w + c.w) + (d.w + e.w)) + xv.w;
    *(float4*)(out + i) = o;
}

// ---------------------------------------------------------------------------
extern "C" void kernel_launch(void* const* d_in, const int* in_sizes, int n_in,
                              void* d_out, int out_size)
{
    const float* x     = (const float*)d_in[0];
    const float* Wq    = (const float*)d_in[1];
    const float* bq    = (const float*)d_in[2];
    const float* Wk    = (const float*)d_in[3];
    const float* bk    = (const float*)d_in[4];
    const float* Wv    = (const float*)d_in[5];
    const float* bv    = (const float*)d_in[6];
    const float* gamma = (const float*)d_in[7];
    float* out = (float*)d_out;

    qkv_kernel<<<dim3(HW / 128, NBAT), 512>>>(x, Wq, bq, Wk, bk, Wv, bv);
    denom_kernel<<<dim3(HW / 128, NSPL, NBAT), 256>>>();
    vscale_kernel<<<dim3(HW / 512, NBAT), 256>>>();
    attn_kernel<<<dim3(HW / 128, NS, NBAT), 256>>>();
    combine_kernel<<<PSZ / 1024, 256>>>(x, gamma, out);
}